// round 12
// baseline (speedup 1.0000x reference)
#include <cuda_runtime.h>

#define T_SEQ 2048
#define B_SZ  512
#define NTICK (T_SEQ / 2 + 3)   // 2 steps/tick + pipeline fill/drain (head stage adds 1)

typedef unsigned long long u64;

// ---------- packed f32x2 helpers ----------
__device__ __forceinline__ u64 pack2(float a, float b) {
    u64 d; asm("mov.b64 %0,{%1,%2};" : "=l"(d) : "f"(a), "f"(b)); return d;
}
__device__ __forceinline__ void unpack2(u64 v, float& a, float& b) {
    asm("mov.b64 {%0,%1},%2;" : "=f"(a), "=f"(b) : "l"(v));
}
__device__ __forceinline__ u64 fma2(u64 a, u64 b, u64 c) {
    u64 d; asm("fma.rn.f32x2 %0,%1,%2,%3;" : "=l"(d) : "l"(a), "l"(b), "l"(c)); return d;
}
__device__ __forceinline__ u64 add2(u64 a, u64 b) {
    u64 d; asm("add.rn.f32x2 %0,%1,%2;" : "=l"(d) : "l"(a), "l"(b)); return d;
}

// ---------- activations via HW MUFU tanh (validated R6-R11, err ~5e-6) ----------
__device__ __forceinline__ float htanh(float x) {
    float y; asm("tanh.approx.f32 %0,%1;" : "=f"(y) : "f"(x)); return y;
}
__device__ __forceinline__ float sigm(float x)  { return fmaf(htanh(0.5f * x), 0.5f, 0.5f); }
__device__ __forceinline__ float tanhf_(float x){ return htanh(x); }

// Gate-pair matvec: two half-chains (k 0..15 / 16..31) per accumulator,
// combined with one add2 -> 4 independent 16-deep chains (validated R11).
__device__ __forceinline__ void matvec(const ulonglong2* __restrict__ hv,
                                       const u64* __restrict__ w_if,
                                       const u64* __restrict__ w_go,
                                       u64 if0, u64 go0, u64& aif, u64& ago)
{
    u64 aL = if0, gL = go0, aH = 0ull, gH = 0ull;
#pragma unroll
    for (int m = 0; m < 8; m++) {
        ulonglong2 h2 = hv[m];
        aL = fma2(h2.x, w_if[2*m],   aL);
        gL = fma2(h2.x, w_go[2*m],   gL);
        aL = fma2(h2.y, w_if[2*m+1], aL);
        gL = fma2(h2.y, w_go[2*m+1], gL);
    }
#pragma unroll
    for (int m = 8; m < 16; m++) {
        ulonglong2 h2 = hv[m];
        aH = fma2(h2.x, w_if[2*m],   aH);
        gH = fma2(h2.x, w_go[2*m],   gH);
        aH = fma2(h2.y, w_if[2*m+1], aH);
        gH = fma2(h2.y, w_go[2*m+1], gH);
    }
    aif = add2(aL, aH);
    ago = add2(gL, gH);
}

__device__ __forceinline__ float cellstep(u64 aif, u64 ago, float& c) {
    float gi, gf, gg, go;
    unpack2(aif, gi, gf); unpack2(ago, gg, go);
    gi = sigm(gi); gf = sigm(gf); gg = tanhf_(gg); go = sigm(go);
    c = gf * c + gi * gg;
    return go * tanhf_(c);
}

// =====================================================================
// Fully fused 2-layer LSTM + dense head. One trio (3 warps) per block,
// TWO TIMESTEPS PER BARRIER TICK (R11 skeleton, validated):
//   role 0: layer-0 cell          (h0 pair of tick m)
//   role 1: dense head (h1 of tick m-3) + layer-1 input proj (tick m-1)
//   role 2: layer-1 cell          (h1 pair of tick m-2)
// Head lives in role1 — the least-loaded warp, off every critical path;
// its two shfl-butterfly chains complete underneath the proj matvec.
// This removes the separate head kernel and the 134MB g_h1 round-trip.
// role = (wid + blockIdx) % 3 (validated SMSP role mixing).
// 512 blocks x 96 threads, 4 blocks/SM.
// =====================================================================
__global__ void __launch_bounds__(96, 4)
k_fused(const float* __restrict__ x,
        const float* __restrict__ Wih0, const float* __restrict__ Whh0,
        const float* __restrict__ bih0, const float* __restrict__ bhh0,
        const float* __restrict__ Wih1, const float* __restrict__ Whh1,
        const float* __restrict__ bih1, const float* __restrict__ bhh1,
        const float* __restrict__ Wd,   const float* __restrict__ bd,
        float* __restrict__ out)
{
    __shared__ __align__(16) float h0ring[2][2][64];   // [slot][step] duplicated {h,h}
    __shared__ __align__(16) u64   pring[2][2][64];    // [slot][step] {i,f}/{g,o}
    __shared__ __align__(16) float h1ring[2][2][64];

    const int tid  = threadIdx.x;
    const int wid  = tid >> 5, j = tid & 31;
    const int role = (wid + blockIdx.x) % 3;           // rotated role mapping
    const int b    = blockIdx.x;

    // zero initial hidden states (all ring slots)
    for (int i = tid; i < 2 * 2 * 64; i += 96) {
        ((float*)h0ring)[i] = 0.f;
        ((float*)h1ring)[i] = 0.f;
    }

    // per-role weight matrix -> 64 u64 regs of gate-pair columns
    const float* Wsrc = (role == 0) ? Whh0 : (role == 1) ? Wih1 : Whh1;
    u64 w_if[32], w_go[32];
#pragma unroll
    for (int k = 0; k < 32; k++) {
        w_if[k] = pack2(Wsrc[j * 32 + k],        Wsrc[(32 + j) * 32 + k]);
        w_go[k] = pack2(Wsrc[(64 + j) * 32 + k], Wsrc[(96 + j) * 32 + k]);
    }

    u64 wx_if = 0, wx_go = 0, bs_if = 0, bs_go = 0;
    if (role == 0) {
        wx_if = pack2(Wih0[j],      Wih0[32 + j]);
        wx_go = pack2(Wih0[64 + j], Wih0[96 + j]);
        bs_if = pack2(bih0[j] + bhh0[j],           bih0[32 + j] + bhh0[32 + j]);
        bs_go = pack2(bih0[64 + j] + bhh0[64 + j], bih0[96 + j] + bhh0[96 + j]);
    } else if (role == 1) {
        bs_if = pack2(bih1[j] + bhh1[j],           bih1[32 + j] + bhh1[32 + j]);
        bs_go = pack2(bih1[64 + j] + bhh1[64 + j], bih1[96 + j] + bhh1[96 + j]);
    }
    const float wd  = Wd[j];
    const float bdv = bd[0];

    float c   = 0.f;                   // cell state (roles 0 and 2)
    float xtA = x[b];                  // x[0], x[1]  (IN == 1)
    float xtB = x[B_SZ + b];

    __syncthreads();                   // init visible

#pragma unroll 1
    for (int n = 0; n < NTICK; n++) {
        if (role == 0) {
            if (n < T_SEQ / 2) {
                const int t0 = 2 * n;
                const int tpA = (t0 + 2 < T_SEQ) ? (t0 + 2) : (T_SEQ - 1);
                const int tpB = (t0 + 3 < T_SEQ) ? (t0 + 3) : (T_SEQ - 1);
                float xnA = x[tpA * B_SZ + b];         // prefetch next tick's x
                float xnB = x[tpB * B_SZ + b];
                u64 aif, ago;
                // step A: h0[2n] from h0[2n-1] (prev tick slot, step 1)
                matvec(reinterpret_cast<const ulonglong2*>(h0ring[(n + 1) & 1][1]),
                       w_if, w_go,
                       fma2(pack2(xtA, xtA), wx_if, bs_if),
                       fma2(pack2(xtA, xtA), wx_go, bs_go), aif, ago);
                float hA = cellstep(aif, ago, c);
                reinterpret_cast<u64*>(h0ring[n & 1][0])[j] = pack2(hA, hA);
                __syncwarp();
                // step B: h0[2n+1] from fresh h0[2n]
                matvec(reinterpret_cast<const ulonglong2*>(h0ring[n & 1][0]),
                       w_if, w_go,
                       fma2(pack2(xtB, xtB), wx_if, bs_if),
                       fma2(pack2(xtB, xtB), wx_go, bs_go), aif, ago);
                float hB = cellstep(aif, ago, c);
                reinterpret_cast<u64*>(h0ring[n & 1][1])[j] = pack2(hB, hB);
                xtA = xnA; xtB = xnB;
            }
        } else if (role == 1) {
            // ---- dense head for h1 pair written at tick n-1 (t0 = 2(n-3)) ----
            // Off the critical path: shfl chains retire under the proj matvec.
            float yA = 0.f, yB = 0.f; int th = 0;
            if (n >= 3 && n <= T_SEQ / 2 + 2) {
                const int s = (n - 1) & 1;
                th = 2 * (n - 3);
                float hA = h1ring[s][0][2 * j];        // duplicated pair: [2j] = h_j
                float hB = h1ring[s][1][2 * j];
                yA = hA * wd; yB = hB * wd;
#pragma unroll
                for (int off = 16; off > 0; off >>= 1) {   // two interleaved butterflies
                    yA += __shfl_xor_sync(0xffffffffu, yA, off);
                    yB += __shfl_xor_sync(0xffffffffu, yB, off);
                }
            }
            // ---- layer-1 input projection for tick n-1 ----
            if (n >= 1 && n <= T_SEQ / 2) {
                const int s = (n - 1) & 1;
                u64 aifA, agoA, aifB, agoB;   // two INDEPENDENT matvecs
                matvec(reinterpret_cast<const ulonglong2*>(h0ring[s][0]),
                       w_if, w_go, bs_if, bs_go, aifA, agoA);
                matvec(reinterpret_cast<const ulonglong2*>(h0ring[s][1]),
                       w_if, w_go, bs_if, bs_go, aifB, agoB);
                pring[s][0][j]      = aifA;
                pring[s][0][32 + j] = agoA;
                pring[s][1][j]      = aifB;
                pring[s][1][32 + j] = agoB;
            }
            // ---- head stores (dependency chain ended during matvec) ----
            if (n >= 3 && n <= T_SEQ / 2 + 2 && j == 0) {
                out[th * B_SZ + b]       = yA + bdv;
                out[(th + 1) * B_SZ + b] = yB + bdv;
            }
        } else {
            if (n >= 2 && n <= T_SEQ / 2 + 1) {
                const int s = n & 1;                   // slot (n-2)&1 == n&1
                u64 aif, ago;
                // step A: h1[t0] from h1[t0-1] (prev tick slot, step 1)
                matvec(reinterpret_cast<const ulonglong2*>(h1ring[(n + 1) & 1][1]),
                       w_if, w_go, pring[s][0][j], pring[s][0][32 + j], aif, ago);
                float hA = cellstep(aif, ago, c);
                reinterpret_cast<u64*>(h1ring[s][0])[j] = pack2(hA, hA);
                __syncwarp();
                // step B: h1[t0+1] from fresh h1[t0]
                matvec(reinterpret_cast<const ulonglong2*>(h1ring[s][0]),
                       w_if, w_go, pring[s][1][j], pring[s][1][32 + j], aif, ago);
                float hB = cellstep(aif, ago, c);
                reinterpret_cast<u64*>(h1ring[s][1])[j] = pack2(hB, hB);
            }
        }
        __syncthreads();               // one 3-warp barrier per 2 timesteps
    }
}

// =====================================================================
extern "C" void kernel_launch(void* const* d_in, const int* in_sizes, int n_in,
                              void* d_out, int out_size)
{
    const float* x    = (const float*)d_in[0];
    const float* Wih0 = (const float*)d_in[1];
    const float* Whh0 = (const float*)d_in[2];
    const float* bih0 = (const float*)d_in[3];
    const float* bhh0 = (const float*)d_in[4];
    const float* Wih1 = (const float*)d_in[5];
    const float* Whh1 = (const float*)d_in[6];
    const float* bih1 = (const float*)d_in[7];
    const float* bhh1 = (const float*)d_in[8];
    const float* Wd   = (const float*)d_in[9];
    const float* bd   = (const float*)d_in[10];

    k_fused<<<512, 96>>>(x, Wih0, Whh0, bih0, bhh0,
                         Wih1, Whh1, bih1, bhh1, Wd, bd, (float*)d_out);
}

// round 13
// speedup vs baseline: 1.1661x; 1.1661x over previous
#include <cuda_runtime.h>

#define T_SEQ 2048
#define B_SZ  512
#define NTICK (T_SEQ / 4 + 2)   // 4 timesteps per tick + 2 pipeline fill

// h1 scratch for the deferred dense head (134 MB)
__device__ __align__(16) float g_h1[(size_t)T_SEQ * B_SZ * 32];

typedef unsigned long long u64;

// ---------- packed f32x2 helpers ----------
__device__ __forceinline__ u64 pack2(float a, float b) {
    u64 d; asm("mov.b64 %0,{%1,%2};" : "=l"(d) : "f"(a), "f"(b)); return d;
}
__device__ __forceinline__ void unpack2(u64 v, float& a, float& b) {
    asm("mov.b64 {%0,%1},%2;" : "=f"(a), "=f"(b) : "l"(v));
}
__device__ __forceinline__ u64 fma2(u64 a, u64 b, u64 c) {
    u64 d; asm("fma.rn.f32x2 %0,%1,%2,%3;" : "=l"(d) : "l"(a), "l"(b), "l"(c)); return d;
}
__device__ __forceinline__ u64 add2(u64 a, u64 b) {
    u64 d; asm("add.rn.f32x2 %0,%1,%2;" : "=l"(d) : "l"(a), "l"(b)); return d;
}

// ---------- activations via HW MUFU tanh (validated R6-R11, err ~5e-6) ----------
__device__ __forceinline__ float htanh(float x) {
    float y; asm("tanh.approx.f32 %0,%1;" : "=f"(y) : "f"(x)); return y;
}
__device__ __forceinline__ float sigm(float x)  { return fmaf(htanh(0.5f * x), 0.5f, 0.5f); }
__device__ __forceinline__ float tanhf_(float x){ return htanh(x); }

// Gate-pair matvec: two half-chains (k 0..15 / 16..31) per accumulator,
// combined with one add2 -> 4 independent 16-deep chains (validated R11).
__device__ __forceinline__ void matvec(const ulonglong2* __restrict__ hv,
                                       const u64* __restrict__ w_if,
                                       const u64* __restrict__ w_go,
                                       u64 if0, u64 go0, u64& aif, u64& ago)
{
    u64 aL = if0, gL = go0, aH = 0ull, gH = 0ull;
#pragma unroll
    for (int m = 0; m < 8; m++) {
        ulonglong2 h2 = hv[m];
        aL = fma2(h2.x, w_if[2*m],   aL);
        gL = fma2(h2.x, w_go[2*m],   gL);
        aL = fma2(h2.y, w_if[2*m+1], aL);
        gL = fma2(h2.y, w_go[2*m+1], gL);
    }
#pragma unroll
    for (int m = 8; m < 16; m++) {
        ulonglong2 h2 = hv[m];
        aH = fma2(h2.x, w_if[2*m],   aH);
        gH = fma2(h2.x, w_go[2*m],   gH);
        aH = fma2(h2.y, w_if[2*m+1], aH);
        gH = fma2(h2.y, w_go[2*m+1], gH);
    }
    aif = add2(aL, aH);
    ago = add2(gL, gH);
}

__device__ __forceinline__ float cellstep(u64 aif, u64 ago, float& c) {
    float gi, gf, gg, go;
    unpack2(aif, gi, gf); unpack2(ago, gg, go);
    gi = sigm(gi); gf = sigm(gf); gg = tanhf_(gg); go = sigm(go);
    c = gf * c + gi * gg;
    return go * tanhf_(c);
}

// =====================================================================
// Fused 2-layer LSTM. One trio (3 warps) per block (R11 skeleton),
// FOUR TIMESTEPS PER BARRIER TICK:
//   role 0: layer-0 cell       (h0[4m..4m+3] at tick m)
//   role 1: layer-1 input proj (xp1 of tick m-1; 4 independent matvecs,
//                               issued as two R11-style pairs to bound regs)
//   role 2: layer-1 cell       (h1 of tick m-2)
// role = (wid + blockIdx) % 3 (validated SMSP role mixing).
// Rings: [tick-slot][step-in-tick 0..3]; intra-tick fresh-h reads use
// __syncwarp; one __syncthreads per 4 timesteps.
// 512 blocks x 96 threads, 4 blocks/SM (all resident).
// =====================================================================
__global__ void __launch_bounds__(96, 4)
k_fused(const float* __restrict__ x,
        const float* __restrict__ Wih0, const float* __restrict__ Whh0,
        const float* __restrict__ bih0, const float* __restrict__ bhh0,
        const float* __restrict__ Wih1, const float* __restrict__ Whh1,
        const float* __restrict__ bih1, const float* __restrict__ bhh1)
{
    __shared__ __align__(16) float h0ring[2][4][64];   // [slot][step] duplicated {h,h}
    __shared__ __align__(16) u64   pring[2][4][64];    // [slot][step] {i,f}/{g,o}
    __shared__ __align__(16) float h1ring[2][4][64];

    const int tid  = threadIdx.x;
    const int wid  = tid >> 5, j = tid & 31;
    const int role = (wid + blockIdx.x) % 3;           // rotated role mapping
    const int b    = blockIdx.x;

    // zero initial hidden states (all ring slots)
    for (int i = tid; i < 2 * 4 * 64; i += 96) {
        ((float*)h0ring)[i] = 0.f;
        ((float*)h1ring)[i] = 0.f;
    }

    // per-role weight matrix -> 64 u64 regs of gate-pair columns
    const float* Wsrc = (role == 0) ? Whh0 : (role == 1) ? Wih1 : Whh1;
    u64 w_if[32], w_go[32];
#pragma unroll
    for (int k = 0; k < 32; k++) {
        w_if[k] = pack2(Wsrc[j * 32 + k],        Wsrc[(32 + j) * 32 + k]);
        w_go[k] = pack2(Wsrc[(64 + j) * 32 + k], Wsrc[(96 + j) * 32 + k]);
    }

    u64 wx_if = 0, wx_go = 0, bs_if = 0, bs_go = 0;
    if (role == 0) {
        wx_if = pack2(Wih0[j],      Wih0[32 + j]);
        wx_go = pack2(Wih0[64 + j], Wih0[96 + j]);
        bs_if = pack2(bih0[j] + bhh0[j],           bih0[32 + j] + bhh0[32 + j]);
        bs_go = pack2(bih0[64 + j] + bhh0[64 + j], bih0[96 + j] + bhh0[96 + j]);
    } else if (role == 1) {
        bs_if = pack2(bih1[j] + bhh1[j],           bih1[32 + j] + bhh1[32 + j]);
        bs_go = pack2(bih1[64 + j] + bhh1[64 + j], bih1[96 + j] + bhh1[96 + j]);
    }

    float c = 0.f;                     // cell state (roles 0 and 2)
    float xt0 = x[b];                  // x[0..3]  (IN == 1)
    float xt1 = x[1 * B_SZ + b];
    float xt2 = x[2 * B_SZ + b];
    float xt3 = x[3 * B_SZ + b];

    __syncthreads();                   // init visible

#pragma unroll 1
    for (int n = 0; n < NTICK; n++) {
        if (role == 0) {
            if (n < T_SEQ / 4) {
                const int t0 = 4 * n;
                // prefetch next tick's x quad (clamped at tail)
                const int p0 = (t0 + 4 < T_SEQ) ? (t0 + 4) : (T_SEQ - 1);
                const int p1 = (t0 + 5 < T_SEQ) ? (t0 + 5) : (T_SEQ - 1);
                const int p2 = (t0 + 6 < T_SEQ) ? (t0 + 6) : (T_SEQ - 1);
                const int p3 = (t0 + 7 < T_SEQ) ? (t0 + 7) : (T_SEQ - 1);
                float xn0 = x[p0 * B_SZ + b], xn1 = x[p1 * B_SZ + b];
                float xn2 = x[p2 * B_SZ + b], xn3 = x[p3 * B_SZ + b];
                const int s = n & 1;
                u64 aif, ago;
                // step 0: from prev tick's step 3
                matvec(reinterpret_cast<const ulonglong2*>(h0ring[s ^ 1][3]),
                       w_if, w_go,
                       fma2(pack2(xt0, xt0), wx_if, bs_if),
                       fma2(pack2(xt0, xt0), wx_go, bs_go), aif, ago);
                float h = cellstep(aif, ago, c);
                reinterpret_cast<u64*>(h0ring[s][0])[j] = pack2(h, h);
                __syncwarp();
                // step 1
                matvec(reinterpret_cast<const ulonglong2*>(h0ring[s][0]),
                       w_if, w_go,
                       fma2(pack2(xt1, xt1), wx_if, bs_if),
                       fma2(pack2(xt1, xt1), wx_go, bs_go), aif, ago);
                h = cellstep(aif, ago, c);
                reinterpret_cast<u64*>(h0ring[s][1])[j] = pack2(h, h);
                __syncwarp();
                // step 2
                matvec(reinterpret_cast<const ulonglong2*>(h0ring[s][1]),
                       w_if, w_go,
                       fma2(pack2(xt2, xt2), wx_if, bs_if),
                       fma2(pack2(xt2, xt2), wx_go, bs_go), aif, ago);
                h = cellstep(aif, ago, c);
                reinterpret_cast<u64*>(h0ring[s][2])[j] = pack2(h, h);
                __syncwarp();
                // step 3
                matvec(reinterpret_cast<const ulonglong2*>(h0ring[s][2]),
                       w_if, w_go,
                       fma2(pack2(xt3, xt3), wx_if, bs_if),
                       fma2(pack2(xt3, xt3), wx_go, bs_go), aif, ago);
                h = cellstep(aif, ago, c);
                reinterpret_cast<u64*>(h0ring[s][3])[j] = pack2(h, h);
                xt0 = xn0; xt1 = xn1; xt2 = xn2; xt3 = xn3;
            }
        } else if (role == 1) {
            if (n >= 1 && n <= T_SEQ / 4) {
                const int s = (n - 1) & 1;
                // two independent matvec pairs (R11 register pattern)
                {
                    u64 aifA, agoA, aifB, agoB;
                    matvec(reinterpret_cast<const ulonglong2*>(h0ring[s][0]),
                           w_if, w_go, bs_if, bs_go, aifA, agoA);
                    matvec(reinterpret_cast<const ulonglong2*>(h0ring[s][1]),
                           w_if, w_go, bs_if, bs_go, aifB, agoB);
                    pring[s][0][j]      = aifA;
                    pring[s][0][32 + j] = agoA;
                    pring[s][1][j]      = aifB;
                    pring[s][1][32 + j] = agoB;
                }
                {
                    u64 aifA, agoA, aifB, agoB;
                    matvec(reinterpret_cast<const ulonglong2*>(h0ring[s][2]),
                           w_if, w_go, bs_if, bs_go, aifA, agoA);
                    matvec(reinterpret_cast<const ulonglong2*>(h0ring[s][3]),
                           w_if, w_go, bs_if, bs_go, aifB, agoB);
                    pring[s][2][j]      = aifA;
                    pring[s][2][32 + j] = agoA;
                    pring[s][3][j]      = aifB;
                    pring[s][3][32 + j] = agoB;
                }
            }
        } else {
            if (n >= 2) {
                const int t0 = 4 * (n - 2);
                const int s  = n & 1;                  // slot (n-2)&1 == n&1
                float* h1o = g_h1 + (size_t)t0 * (B_SZ * 32) + b * 32 + j;
                u64 aif, ago;
                // step 0: from prev tick's step 3
                matvec(reinterpret_cast<const ulonglong2*>(h1ring[s ^ 1][3]),
                       w_if, w_go, pring[s][0][j], pring[s][0][32 + j], aif, ago);
                float h = cellstep(aif, ago, c);
                reinterpret_cast<u64*>(h1ring[s][0])[j] = pack2(h, h);
                h1o[0] = h;
                __syncwarp();
                // step 1
                matvec(reinterpret_cast<const ulonglong2*>(h1ring[s][0]),
                       w_if, w_go, pring[s][1][j], pring[s][1][32 + j], aif, ago);
                h = cellstep(aif, ago, c);
                reinterpret_cast<u64*>(h1ring[s][1])[j] = pack2(h, h);
                h1o[B_SZ * 32] = h;
                __syncwarp();
                // step 2
                matvec(reinterpret_cast<const ulonglong2*>(h1ring[s][1]),
                       w_if, w_go, pring[s][2][j], pring[s][2][32 + j], aif, ago);
                h = cellstep(aif, ago, c);
                reinterpret_cast<u64*>(h1ring[s][2])[j] = pack2(h, h);
                h1o[2 * B_SZ * 32] = h;
                __syncwarp();
                // step 3
                matvec(reinterpret_cast<const ulonglong2*>(h1ring[s][2]),
                       w_if, w_go, pring[s][3][j], pring[s][3][32 + j], aif, ago);
                h = cellstep(aif, ago, c);
                reinterpret_cast<u64*>(h1ring[s][3])[j] = pack2(h, h);
                h1o[3 * B_SZ * 32] = h;
            }
        }
        __syncthreads();               // one 3-warp barrier per 4 timesteps
    }
}

// =====================================================================
// Dense head: out[t,b] = sum_j h1[t,b,j]*Wd[j] + bd. Memory-bound (~30us).
// =====================================================================
__global__ void __launch_bounds__(256)
k_head(const float* __restrict__ Wd, const float* __restrict__ bd,
       float* __restrict__ out)
{
    const int gw = blockIdx.x * 8 + (threadIdx.x >> 5);
    const int j  = threadIdx.x & 31;
    const size_t r = (size_t)gw * 4 + (j >> 3);
    const int q  = j & 7;

    float4 h = reinterpret_cast<const float4*>(g_h1)[r * 8 + q];
    float4 w = reinterpret_cast<const float4*>(Wd)[q];
    float s = h.x * w.x + h.y * w.y + h.z * w.z + h.w * w.w;
    s += __shfl_xor_sync(0xffffffffu, s, 1);
    s += __shfl_xor_sync(0xffffffffu, s, 2);
    s += __shfl_xor_sync(0xffffffffu, s, 4);
    if (q == 0) out[r] = s + bd[0];
}

// =====================================================================
extern "C" void kernel_launch(void* const* d_in, const int* in_sizes, int n_in,
                              void* d_out, int out_size)
{
    const float* x    = (const float*)d_in[0];
    const float* Wih0 = (const float*)d_in[1];
    const float* Whh0 = (const float*)d_in[2];
    const float* bih0 = (const float*)d_in[3];
    const float* bhh0 = (const float*)d_in[4];
    const float* Wih1 = (const float*)d_in[5];
    const float* Whh1 = (const float*)d_in[6];
    const float* bih1 = (const float*)d_in[7];
    const float* bhh1 = (const float*)d_in[8];
    const float* Wd   = (const float*)d_in[9];
    const float* bd   = (const float*)d_in[10];

    k_fused<<<512, 96>>>(x, Wih0, Whh0, bih0, bhh0, Wih1, Whh1, bih1, bhh1);
    k_head<<<32768, 256>>>(Wd, bd, (float*)d_out);
}